// round 12
// baseline (speedup 1.0000x reference)
#include <cuda_runtime.h>
#include <cuda_bf16.h>
#include <math.h>

// Problem constants (fixed shapes)
#define TT 512   // timesteps
#define BB 64    // batch
#define HH 512   // hidden
#define II 128   // input
#define OO 64    // output
#define CL 8     // CTAs per cluster
#define NB 4     // batches per cluster
#define JS 64    // hidden rows per CTA
#define WSS 516  // padded W row stride (conflict-free LDS.128)
#define NTH 512  // threads per CTA (16 warps)
#define ALPHA 0.1f

// Scratch (allowed: __device__ global)
__device__ float g_xproj[(size_t)BB * TT * HH];  // 64 MB

// ---------------- PTX helpers ----------------
__device__ __forceinline__ void fma2(unsigned long long& d,
                                     unsigned long long a,
                                     unsigned long long b) {
    asm("fma.rn.f32x2 %0, %1, %2, %0;" : "+l"(d) : "l"(a), "l"(b));
}
__device__ __forceinline__ float hadd2(unsigned long long v) {
    unsigned lo, hi;
    asm("mov.b64 {%0,%1}, %2;" : "=r"(lo), "=r"(hi) : "l"(v));
    return __uint_as_float(lo) + __uint_as_float(hi);
}
__device__ __forceinline__ unsigned long long pack2(float x, float y) {
    unsigned long long r;
    asm("mov.b64 %0, {%1, %2};" : "=l"(r) : "f"(x), "f"(y));
    return r;
}
__device__ __forceinline__ unsigned smem_u32(const void* p) {
    unsigned a;
    asm("{ .reg .u64 t; cvta.to.shared.u64 t, %1; cvt.u32.u64 %0, t; }"
        : "=r"(a) : "l"(p));
    return a;
}
__device__ __forceinline__ unsigned mapa_u32(unsigned addr, unsigned rank) {
    unsigned r;
    asm("mapa.shared::cluster.u32 %0, %1, %2;" : "=r"(r) : "r"(addr), "r"(rank));
    return r;
}
__device__ __forceinline__ void st_async64(unsigned addr, unsigned long long v,
                                           unsigned mbar) {
    asm volatile(
        "st.async.shared::cluster.mbarrier::complete_tx::bytes.b64 [%0], %1, [%2];"
        :: "r"(addr), "l"(v), "r"(mbar) : "memory");
}
__device__ __forceinline__ void mbar_init(unsigned addr, unsigned cnt) {
    asm volatile("mbarrier.init.shared.b64 [%0], %1;" :: "r"(addr), "r"(cnt) : "memory");
}
__device__ __forceinline__ void mbar_arrive(unsigned addr) {
    asm volatile("mbarrier.arrive.release.cluster.shared::cta.b64 _, [%0];"
                 :: "r"(addr) : "memory");
}
__device__ __forceinline__ void mbar_arrive_expect(unsigned addr, unsigned tx) {
    asm volatile("mbarrier.arrive.expect_tx.release.cluster.shared::cta.b64 _, [%0], %1;"
                 :: "r"(addr), "r"(tx) : "memory");
}
__device__ __forceinline__ void mbar_wait(unsigned addr, unsigned phase) {
    asm volatile(
        "{\n\t"
        ".reg .pred P;\n\t"
        "LW_%=:\n\t"
        "mbarrier.try_wait.parity.acquire.cluster.shared::cta.b64 P, [%0], %1, 0x989680;\n\t"
        "@P bra.uni LD_%=;\n\t"
        "bra.uni LW_%=;\n\t"
        "LD_%=:\n\t"
        "}"
        :: "r"(addr), "r"(phase) : "memory");
}
__device__ __forceinline__ float fast_tanh(float x) {
    float e = __expf(2.0f * x);
    return 1.0f - __fdividef(2.0f, e + 1.0f);
}

// ---------------------------------------------------------------------------
// Phase 1: x_proj[b,t,h] = sum_i inputs[b,t,i] * W_in[h,i]
// ---------------------------------------------------------------------------
__global__ void __launch_bounds__(256) xproj_kernel(const float* __restrict__ A,
                                                    const float* __restrict__ Win) {
    __shared__ float As[64 * 65];
    __shared__ float Bs[64 * 65];
    int mb = blockIdx.x;
    int hb = blockIdx.y;
    int tid = threadIdx.x;
    int tx = tid & 15, ty = tid >> 4;

    float acc[4][4];
#pragma unroll
    for (int i = 0; i < 4; ++i)
#pragma unroll
        for (int j = 0; j < 4; ++j) acc[i][j] = 0.f;

    for (int kc = 0; kc < 2; ++kc) {
#pragma unroll
        for (int i = 0; i < 4; ++i) {
            int f = tid + i * 256;
            int c4 = f & 15, r = f >> 4;
            float4 va = *(const float4*)(A + (size_t)(mb * 64 + r) * II + kc * 64 + c4 * 4);
            As[r * 65 + c4 * 4 + 0] = va.x;
            As[r * 65 + c4 * 4 + 1] = va.y;
            As[r * 65 + c4 * 4 + 2] = va.z;
            As[r * 65 + c4 * 4 + 3] = va.w;
            float4 vb = *(const float4*)(Win + (size_t)(hb * 64 + r) * II + kc * 64 + c4 * 4);
            Bs[r * 65 + c4 * 4 + 0] = vb.x;
            Bs[r * 65 + c4 * 4 + 1] = vb.y;
            Bs[r * 65 + c4 * 4 + 2] = vb.z;
            Bs[r * 65 + c4 * 4 + 3] = vb.w;
        }
        __syncthreads();
#pragma unroll 16
        for (int k = 0; k < 64; ++k) {
            float a0 = As[(ty * 4 + 0) * 65 + k];
            float a1 = As[(ty * 4 + 1) * 65 + k];
            float a2 = As[(ty * 4 + 2) * 65 + k];
            float a3 = As[(ty * 4 + 3) * 65 + k];
            float b0 = Bs[(tx * 4 + 0) * 65 + k];
            float b1 = Bs[(tx * 4 + 1) * 65 + k];
            float b2 = Bs[(tx * 4 + 2) * 65 + k];
            float b3 = Bs[(tx * 4 + 3) * 65 + k];
            acc[0][0] += a0 * b0; acc[0][1] += a0 * b1; acc[0][2] += a0 * b2; acc[0][3] += a0 * b3;
            acc[1][0] += a1 * b0; acc[1][1] += a1 * b1; acc[1][2] += a1 * b2; acc[1][3] += a1 * b3;
            acc[2][0] += a2 * b0; acc[2][1] += a2 * b1; acc[2][2] += a2 * b2; acc[2][3] += a2 * b3;
            acc[3][0] += a3 * b0; acc[3][1] += a3 * b1; acc[3][2] += a3 * b2; acc[3][3] += a3 * b3;
        }
        __syncthreads();
    }
#pragma unroll
    for (int i = 0; i < 4; ++i) {
        float4 v = make_float4(acc[i][0], acc[i][1], acc[i][2], acc[i][3]);
        *(float4*)(g_xproj + (size_t)(mb * 64 + ty * 4 + i) * HH + hb * 64 + tx * 4) = v;
    }
}

// ---------------------------------------------------------------------------
// SMEM layout (float offsets):
//   [0..4)            : 2 mbarriers (2 x u64)
//   [4..33028)        : Ws   64 rows x 516 stride
//   [33028..35076)    : hs0  [srcCTA(8)][batch(4)][64]
//   [35076..37124)    : hs1
//   [37124..39172)    : red  [kslice(8)][256]
//   [39172..43268)    : WoS  [8 rows][512]
//   [43268..43332)    : bsl  [64]
// ---------------------------------------------------------------------------
#define SM_WS  4
#define SM_HS0 33028
#define SM_HS1 35076
#define SM_RED 37124
#define SM_WOS 39172
#define SM_BSL 43268
#define SM_TOT 43332

extern __shared__ float smem2[];

// deferred output: out[tOut] = W_out slice . h (h in [src][b][64] layout)
__device__ __forceinline__ void do_out(const float* __restrict__ h,
                                       const float* __restrict__ WoS,
                                       float* __restrict__ out,
                                       float4 bo4, int wb, int og,
                                       unsigned rank, int cbase, int lane, int tOut) {
    unsigned long long o0 = 0, o1 = 0, o2 = 0, o3 = 0;
#pragma unroll
    for (int m = 0; m < 4; ++m) {
        int hidx = ((lane >> 4) + 2 * m) * 256 + wb * 64 + (lane & 15) * 4;
        ulonglong2 hv = *(const ulonglong2*)&h[hidx];
        int kidx = lane * 4 + m * 128;
        ulonglong2 w0 = *(const ulonglong2*)&WoS[(og + 0) * HH + kidx];
        ulonglong2 w1 = *(const ulonglong2*)&WoS[(og + 1) * HH + kidx];
        ulonglong2 w2 = *(const ulonglong2*)&WoS[(og + 2) * HH + kidx];
        ulonglong2 w3 = *(const ulonglong2*)&WoS[(og + 3) * HH + kidx];
        fma2(o0, w0.x, hv.x); fma2(o0, w0.y, hv.y);
        fma2(o1, w1.x, hv.x); fma2(o1, w1.y, hv.y);
        fma2(o2, w2.x, hv.x); fma2(o2, w2.y, hv.y);
        fma2(o3, w3.x, hv.x); fma2(o3, w3.y, hv.y);
    }
    float f0 = hadd2(o0), f1 = hadd2(o1), f2 = hadd2(o2), f3 = hadd2(o3);
#pragma unroll
    for (int off = 16; off; off >>= 1) {
        f0 += __shfl_xor_sync(0xffffffffu, f0, off);
        f1 += __shfl_xor_sync(0xffffffffu, f1, off);
        f2 += __shfl_xor_sync(0xffffffffu, f2, off);
        f3 += __shfl_xor_sync(0xffffffffu, f3, off);
    }
    if (lane == 0) {
        float4 ov = make_float4(f0 + bo4.x, f1 + bo4.y, f2 + bo4.z, f3 + bo4.w);
        *(float4*)&out[((size_t)(cbase + wb) * TT + tOut) * OO + (int)rank * 8 + og] = ov;
    }
}

__global__ void __launch_bounds__(NTH, 1) rnn_scan_kernel(
    const float* __restrict__ hidden0,
    const float* __restrict__ Wrec,
    const float* __restrict__ bvec,
    const float* __restrict__ Wout,
    const float* __restrict__ bout,
    float* __restrict__ out,      // [B,T,O]
    float* __restrict__ hfinal)   // [B,H]
{
    float* Ws  = smem2 + SM_WS;
    float* hs0 = smem2 + SM_HS0;
    float* hs1 = smem2 + SM_HS1;
    float* red = smem2 + SM_RED;
    float* WoS = smem2 + SM_WOS;
    float* bsl = smem2 + SM_BSL;

    int tid = threadIdx.x;
    int lane = tid & 31, warp = tid >> 5;
    unsigned rank;
    asm("mov.u32 %0, %%cluster_ctarank;" : "=r"(rank));
    int cid = blockIdx.x / CL;
    int cbase = cid * NB;
    int jbase = (int)rank * JS;

    // GEMV roles: warp covers k-slice ks (64 wide), row-half (32 rows)
    int ks = warp & 7;
    int myrow = (warp >> 3) * 32 + lane;   // 0..63
    int kb = ks * 64;

    // owner roles (tid < 256)
    int rb = (tid >> 6) & 3;
    int jl = tid & 63;

    // output roles (warps 8..15)
    int w2 = warp & 7;
    int wb = w2 >> 1;
    int og = (w2 & 1) * 4;
    float4 bo4 = *(const float4*)(bout + (int)rank * 8 + og);

    // ---- load W_rec slice into SMEM (stride 516) ----
    for (int f = tid; f < JS * HH / 4; f += NTH) {
        int j = f >> 7, c4 = f & 127;
        float4 v = *(const float4*)(Wrec + (size_t)(jbase + j) * HH + c4 * 4);
        *(float4*)&Ws[j * WSS + c4 * 4] = v;
    }
    // ---- W_out slice (8 rows) into SMEM ----
    for (int f = tid; f < 8 * HH / 4; f += NTH) {
        int r = f >> 7, c4 = f & 127;
        *(float4*)&WoS[r * HH + c4 * 4] =
            *(const float4*)(Wout + (size_t)((int)rank * 8 + r) * HH + c4 * 4);
    }
    if (tid < JS) bsl[tid] = bvec[jbase + tid];

    // ---- initial hidden into hs0 ([src][b][64] layout) ----
    for (int f = tid; f < CL * NB * 64; f += NTH) {
        int src = f >> 8, bb = (f >> 6) & 3, j = f & 63;
        hs0[f] = hidden0[(size_t)(cbase + bb) * HH + src * 64 + j];
    }

    // ---- mbarriers (count = 512 arrivals per phase) ----
    unsigned barb = smem_u32(smem2);
    if (tid == 0) {
        mbar_init(barb, NTH);
        mbar_init(barb + 8, NTH);
    }
    __syncthreads();
    asm volatile("barrier.cluster.arrive.aligned;" ::: "memory");
    asm volatile("barrier.cluster.wait.aligned;" ::: "memory");

    // ---- DSMEM scatter addressing (owners) ----
    unsigned hs0_u = smem_u32(hs0);
    unsigned dst_off = (unsigned)(((int)rank * 256 + rb * 64 + jl) * 4);
    unsigned d0 = mapa_u32(hs0_u + dst_off, 0);
    unsigned stride = mapa_u32(hs0_u + dst_off, 1) - d0;
    unsigned b0 = mapa_u32(barb, 0);

    const float* cur = hs0;
    unsigned par0 = 0, par1 = 0;

    for (int t = 0; t < TT; ++t) {
        float xp = 0.f;
        if (tid < 256)
            xp = __ldg(&g_xproj[((size_t)(cbase + rb) * TT + t) * HH + jbase + jl]);

        // ---- GEMV slice: row myrow, k in [kb, kb+64), 4 batches ----
        const float* hb = cur + ks * 256;          // [4][64] for this k-slice
        const float* wrow = Ws + myrow * WSS + kb;
        unsigned long long a0 = 0, a1 = 0, a2 = 0, a3 = 0;
#pragma unroll
        for (int m = 0; m < 16; ++m) {
            ulonglong2 wv = *(const ulonglong2*)&wrow[m * 4];
            ulonglong2 h0 = *(const ulonglong2*)&hb[0 * 64 + m * 4];
            ulonglong2 h1 = *(const ulonglong2*)&hb[1 * 64 + m * 4];
            ulonglong2 h2 = *(const ulonglong2*)&hb[2 * 64 + m * 4];
            ulonglong2 h3 = *(const ulonglong2*)&hb[3 * 64 + m * 4];
            fma2(a0, wv.x, h0.x); fma2(a0, wv.y, h0.y);
            fma2(a1, wv.x, h1.x); fma2(a1, wv.y, h1.y);
            fma2(a2, wv.x, h2.x); fma2(a2, wv.y, h2.y);
            fma2(a3, wv.x, h3.x); fma2(a3, wv.y, h3.y);
        }
        red[ks * 256 + 0 * 64 + myrow] = hadd2(a0);
        red[ks * 256 + 1 * 64 + myrow] = hadd2(a1);
        red[ks * 256 + 2 * 64 + myrow] = hadd2(a2);
        red[ks * 256 + 3 * 64 + myrow] = hadd2(a3);
        __syncthreads();

        unsigned idx = (unsigned)((t + 1) & 1);
        if (tid < 256) {
            // ---- owners: reduce, activate, scatter ----
            float s = 0.f;
#pragma unroll
            for (int kk = 0; kk < 8; ++kk) s += red[kk * 256 + rb * 64 + jl];
            float pre = s + bsl[jl] + xp;
            float hp = cur[(int)rank * 256 + rb * 64 + jl];
            float hn = (1.0f - ALPHA) * hp + ALPHA * fast_tanh(pre);

            if (t == TT - 1) hfinal[(size_t)(cbase + rb) * HH + jbase + jl] = hn;

            float hpart = __shfl_xor_sync(0xffffffffu, hn, 1);
            unsigned dbase = d0 + idx * (2048u * 4u);
            unsigned bbase = b0 + idx * 8u;
            if (!(jl & 1)) {
                unsigned long long val = pack2(hn, hpart);
#pragma unroll
                for (int r = 0; r < CL; ++r)
                    st_async64(dbase + (unsigned)r * stride, val,
                               bbase + (unsigned)r * stride);
            }
        } else {
            // ---- output warps: out_{t-1} = W_out . h_t (overlaps scatter) ----
            if (t > 0)
                do_out(cur, WoS, out, bo4, wb, og, rank, cbase, lane, t - 1);
        }

        // arrive (count=512; tid0 also posts expected tx = 8KB)
        unsigned mybar = barb + idx * 8u;
        if (tid == 0) mbar_arrive_expect(mybar, 8192u);
        else          mbar_arrive(mybar);

        unsigned p = idx ? par1 : par0;
        mbar_wait(mybar, p);
        if (idx) par1 ^= 1; else par0 ^= 1;

        cur = idx ? hs1 : hs0;
    }

    // epilogue: out_{TT-1} from final hidden (cur = h_TT)
    if (warp >= 8)
        do_out(cur, WoS, out, bo4, wb, og, rank, cbase, lane, TT - 1);
}

// ---------------------------------------------------------------------------
extern "C" void kernel_launch(void* const* d_in, const int* in_sizes, int n_in,
                              void* d_out, int out_size) {
    const float* inputs = (const float*)d_in[0];   // [B,T,I]
    const float* hidden = (const float*)d_in[1];   // [B,H]
    const float* W_in   = (const float*)d_in[2];   // [H,I]
    const float* W_rec  = (const float*)d_in[3];   // [H,H]
    const float* b      = (const float*)d_in[4];   // [H]
    const float* W_out  = (const float*)d_in[5];   // [O,H]
    const float* b_out  = (const float*)d_in[6];   // [O]

    float* out    = (float*)d_out;                 // [B,T,O]
    float* hfinal = out + (size_t)BB * TT * OO;    // [B,H]

    xproj_kernel<<<dim3(512, 8), 256>>>(inputs, W_in);

    const size_t smem_bytes = (size_t)SM_TOT * sizeof(float);
    cudaFuncSetAttribute(rnn_scan_kernel, cudaFuncAttributeMaxDynamicSharedMemorySize,
                         (int)smem_bytes);

    cudaLaunchConfig_t cfg = {};
    cfg.gridDim = dim3((BB / NB) * CL);   // 16 clusters * 8 CTAs = 128 blocks
    cfg.blockDim = dim3(NTH);
    cfg.dynamicSmemBytes = smem_bytes;
    cudaLaunchAttribute attrs[1];
    attrs[0].id = cudaLaunchAttributeClusterDimension;
    attrs[0].val.clusterDim.x = CL;
    attrs[0].val.clusterDim.y = 1;
    attrs[0].val.clusterDim.z = 1;
    cfg.attrs = attrs;
    cfg.numAttrs = 1;

    cudaLaunchKernelEx(&cfg, rnn_scan_kernel, hidden, W_rec, b, W_out, b_out, out, hfinal);
}

// round 13
// speedup vs baseline: 1.2053x; 1.2053x over previous
#include <cuda_runtime.h>
#include <cuda_bf16.h>
#include <math.h>

// Problem constants (fixed shapes)
#define TT 512   // timesteps
#define BB 64    // batch
#define HH 512   // hidden
#define II 128   // input
#define OO 64    // output
#define CL 8     // CTAs per cluster
#define NB 4     // batches per cluster
#define JS 64    // hidden rows per CTA
#define ALPHA 0.1f

// Scratch (allowed: __device__ global)
__device__ float g_xproj[(size_t)BB * TT * HH];  // 64 MB

// ---------------- PTX helpers ----------------
__device__ __forceinline__ void fma2(unsigned long long& d,
                                     unsigned long long a,
                                     unsigned long long b) {
    asm("fma.rn.f32x2 %0, %1, %2, %0;" : "+l"(d) : "l"(a), "l"(b));
}
__device__ __forceinline__ float hadd2(unsigned long long v) {
    unsigned lo, hi;
    asm("mov.b64 {%0,%1}, %2;" : "=r"(lo), "=r"(hi) : "l"(v));
    return __uint_as_float(lo) + __uint_as_float(hi);
}
__device__ __forceinline__ unsigned long long pack2(float x, float y) {
    unsigned long long r;
    asm("mov.b64 %0, {%1, %2};" : "=l"(r) : "f"(x), "f"(y));
    return r;
}
__device__ __forceinline__ unsigned smem_u32(const void* p) {
    unsigned a;
    asm("{ .reg .u64 t; cvta.to.shared.u64 t, %1; cvt.u32.u64 %0, t; }"
        : "=r"(a) : "l"(p));
    return a;
}
__device__ __forceinline__ unsigned mapa_u32(unsigned addr, unsigned rank) {
    unsigned r;
    asm("mapa.shared::cluster.u32 %0, %1, %2;" : "=r"(r) : "r"(addr), "r"(rank));
    return r;
}
__device__ __forceinline__ void st_cluster64(unsigned addr, unsigned long long v) {
    asm volatile("st.shared::cluster.b64 [%0], %1;" :: "r"(addr), "l"(v) : "memory");
}
__device__ __forceinline__ void mbar_init(unsigned addr, unsigned cnt) {
    asm volatile("mbarrier.init.shared.b64 [%0], %1;" :: "r"(addr), "r"(cnt) : "memory");
}
__device__ __forceinline__ void fence_cluster() {
    asm volatile("fence.acq_rel.cluster;" ::: "memory");
}
__device__ __forceinline__ void mbar_arrive_remote(unsigned addr) {
    asm volatile("mbarrier.arrive.release.cluster.shared::cluster.b64 _, [%0];"
                 :: "r"(addr) : "memory");
}
__device__ __forceinline__ void mbar_wait(unsigned addr, unsigned phase) {
    asm volatile(
        "{\n\t"
        ".reg .pred P;\n\t"
        "LW_%=:\n\t"
        "mbarrier.try_wait.parity.acquire.cluster.shared::cta.b64 P, [%0], %1, 0x989680;\n\t"
        "@P bra.uni LD_%=;\n\t"
        "bra.uni LW_%=;\n\t"
        "LD_%=:\n\t"
        "}"
        :: "r"(addr), "r"(phase) : "memory");
}
__device__ __forceinline__ float fast_tanh(float x) {
    float e = __expf(2.0f * x);
    return 1.0f - __fdividef(2.0f, e + 1.0f);
}

// ---------------------------------------------------------------------------
// Phase 1: x_proj[b,t,h] = sum_i inputs[b,t,i] * W_in[h,i]
// ---------------------------------------------------------------------------
__global__ void __launch_bounds__(256) xproj_kernel(const float* __restrict__ A,
                                                    const float* __restrict__ Win) {
    __shared__ float As[64 * 65];
    __shared__ float Bs[64 * 65];
    int mb = blockIdx.x;
    int hb = blockIdx.y;
    int tid = threadIdx.x;
    int tx = tid & 15, ty = tid >> 4;

    float acc[4][4];
#pragma unroll
    for (int i = 0; i < 4; ++i)
#pragma unroll
        for (int j = 0; j < 4; ++j) acc[i][j] = 0.f;

    for (int kc = 0; kc < 2; ++kc) {
#pragma unroll
        for (int i = 0; i < 4; ++i) {
            int f = tid + i * 256;
            int c4 = f & 15, r = f >> 4;
            float4 va = *(const float4*)(A + (size_t)(mb * 64 + r) * II + kc * 64 + c4 * 4);
            As[r * 65 + c4 * 4 + 0] = va.x;
            As[r * 65 + c4 * 4 + 1] = va.y;
            As[r * 65 + c4 * 4 + 2] = va.z;
            As[r * 65 + c4 * 4 + 3] = va.w;
            float4 vb = *(const float4*)(Win + (size_t)(hb * 64 + r) * II + kc * 64 + c4 * 4);
            Bs[r * 65 + c4 * 4 + 0] = vb.x;
            Bs[r * 65 + c4 * 4 + 1] = vb.y;
            Bs[r * 65 + c4 * 4 + 2] = vb.z;
            Bs[r * 65 + c4 * 4 + 3] = vb.w;
        }
        __syncthreads();
#pragma unroll 16
        for (int k = 0; k < 64; ++k) {
            float a0 = As[(ty * 4 + 0) * 65 + k];
            float a1 = As[(ty * 4 + 1) * 65 + k];
            float a2 = As[(ty * 4 + 2) * 65 + k];
            float a3 = As[(ty * 4 + 3) * 65 + k];
            float b0 = Bs[(tx * 4 + 0) * 65 + k];
            float b1 = Bs[(tx * 4 + 1) * 65 + k];
            float b2 = Bs[(tx * 4 + 2) * 65 + k];
            float b3 = Bs[(tx * 4 + 3) * 65 + k];
            acc[0][0] += a0 * b0; acc[0][1] += a0 * b1; acc[0][2] += a0 * b2; acc[0][3] += a0 * b3;
            acc[1][0] += a1 * b0; acc[1][1] += a1 * b1; acc[1][2] += a1 * b2; acc[1][3] += a1 * b3;
            acc[2][0] += a2 * b0; acc[2][1] += a2 * b1; acc[2][2] += a2 * b2; acc[2][3] += a2 * b3;
            acc[3][0] += a3 * b0; acc[3][1] += a3 * b1; acc[3][2] += a3 * b2; acc[3][3] += a3 * b3;
        }
        __syncthreads();
    }
#pragma unroll
    for (int i = 0; i < 4; ++i) {
        float4 v = make_float4(acc[i][0], acc[i][1], acc[i][2], acc[i][3]);
        *(float4*)(g_xproj + (size_t)(mb * 64 + ty * 4 + i) * HH + hb * 64 + tx * 4) = v;
    }
}

// ---------------------------------------------------------------------------
// SMEM layout (floats):
//   [0..8)          : 3 mbarriers (3 x u64, padded)
//   [8..6152)       : hs[3]  each [srcCTA(8)][batch(4)][64] = 2048 floats
//   [6152..8200)    : red  [warp(8)][256]
//   [8200..12296)   : WoS  [8 rows][512]
//   [12296..12360)  : bsl  [64]
// ---------------------------------------------------------------------------
#define SM_HS  8
#define SM_RED 6152
#define SM_WOS 8200
#define SM_BSL 12296
#define SM_TOT 12360

extern __shared__ float smem2[];

// deferred output: out[tOut] = W_out slice . h (h in [src][b][64] layout)
__device__ __forceinline__ void do_out(const float* __restrict__ h,
                                       const float* __restrict__ WoS,
                                       float* __restrict__ out,
                                       float4 bo4, int wb, int og,
                                       unsigned rank, int cbase, int lane, int tOut) {
    unsigned long long o0 = 0, o1 = 0, o2 = 0, o3 = 0;
#pragma unroll
    for (int m = 0; m < 4; ++m) {
        int hidx = ((lane >> 4) + 2 * m) * 256 + wb * 64 + (lane & 15) * 4;
        ulonglong2 hv = *(const ulonglong2*)&h[hidx];
        int kidx = lane * 4 + m * 128;
        ulonglong2 w0 = *(const ulonglong2*)&WoS[(og + 0) * HH + kidx];
        ulonglong2 w1 = *(const ulonglong2*)&WoS[(og + 1) * HH + kidx];
        ulonglong2 w2 = *(const ulonglong2*)&WoS[(og + 2) * HH + kidx];
        ulonglong2 w3 = *(const ulonglong2*)&WoS[(og + 3) * HH + kidx];
        fma2(o0, w0.x, hv.x); fma2(o0, w0.y, hv.y);
        fma2(o1, w1.x, hv.x); fma2(o1, w1.y, hv.y);
        fma2(o2, w2.x, hv.x); fma2(o2, w2.y, hv.y);
        fma2(o3, w3.x, hv.x); fma2(o3, w3.y, hv.y);
    }
    float f0 = hadd2(o0), f1 = hadd2(o1), f2 = hadd2(o2), f3 = hadd2(o3);
#pragma unroll
    for (int off = 16; off; off >>= 1) {
        f0 += __shfl_xor_sync(0xffffffffu, f0, off);
        f1 += __shfl_xor_sync(0xffffffffu, f1, off);
        f2 += __shfl_xor_sync(0xffffffffu, f2, off);
        f3 += __shfl_xor_sync(0xffffffffu, f3, off);
    }
    if (lane == 0) {
        float4 ov = make_float4(f0 + bo4.x, f1 + bo4.y, f2 + bo4.z, f3 + bo4.w);
        *(float4*)&out[((size_t)(cbase + wb) * TT + tOut) * OO + (int)rank * 8 + og] = ov;
    }
}

__global__ void __launch_bounds__(256, 1) rnn_scan_kernel(
    const float* __restrict__ hidden0,
    const float* __restrict__ Wrec,
    const float* __restrict__ bvec,
    const float* __restrict__ Wout,
    const float* __restrict__ bout,
    float* __restrict__ out,      // [B,T,O]
    float* __restrict__ hfinal)   // [B,H]
{
    float* hs  = smem2 + SM_HS;    // 3 buffers x 2048
    float* red = smem2 + SM_RED;
    float* WoS = smem2 + SM_WOS;
    float* bsl = smem2 + SM_BSL;

    int tid = threadIdx.x;
    int lane = tid & 31, warp = tid >> 5;
    unsigned rank;
    asm("mov.u32 %0, %%cluster_ctarank;" : "=r"(rank));
    int cid = blockIdx.x / CL;
    int cbase = cid * NB;
    int jbase = (int)rank * JS;
    int rb = tid >> 6;             // batch (0..3)
    int jl = tid & 63;             // local hidden row
    int kb = warp * 64;            // this warp's k range

    // ---- W_rec slice into REGISTERS: rows (lane, lane+32), k in [kb, kb+64) ----
    unsigned long long w0r[32], w1r[32];
    {
        const float4* p0 = (const float4*)(Wrec + (size_t)(jbase + lane) * HH + kb);
        const float4* p1 = (const float4*)(Wrec + (size_t)(jbase + lane + 32) * HH + kb);
#pragma unroll
        for (int i = 0; i < 16; ++i) {
            float4 a = __ldg(p0 + i);
            float4 b = __ldg(p1 + i);
            w0r[2 * i]     = pack2(a.x, a.y);
            w0r[2 * i + 1] = pack2(a.z, a.w);
            w1r[2 * i]     = pack2(b.x, b.y);
            w1r[2 * i + 1] = pack2(b.z, b.w);
        }
    }

    // ---- W_out slice (8 rows) into SMEM ----
    for (int f = tid; f < 8 * HH / 4; f += 256) {
        int r = f >> 7, c4 = f & 127;
        *(float4*)&WoS[r * HH + c4 * 4] =
            *(const float4*)(Wout + (size_t)((int)rank * 8 + r) * HH + c4 * 4);
    }
    if (tid < JS) bsl[tid] = bvec[jbase + tid];

    int wb = warp >> 1;
    int og = (warp & 1) * 4;
    float4 bo4 = *(const float4*)(bout + (int)rank * 8 + og);

    // ---- initial hidden into buffer 0 ([src][b][64] layout) ----
    for (int f = tid; f < CL * NB * 64; f += 256) {
        int src = f >> 8, bb = (f >> 6) & 3, j = f & 63;
        hs[f] = hidden0[(size_t)(cbase + bb) * HH + src * 64 + j];
    }

    // ---- 3 mbarriers, count = 8 (one arrive per source CTA) ----
    unsigned barb = smem_u32(smem2);
    if (tid == 0) {
        mbar_init(barb, 8);
        mbar_init(barb + 8, 8);
        mbar_init(barb + 16, 8);
    }
    __syncthreads();
    asm volatile("barrier.cluster.arrive.aligned;" ::: "memory");
    asm volatile("barrier.cluster.wait.aligned;" ::: "memory");

    // ---- DSMEM scatter addressing ----
    unsigned hs_u = smem_u32(hs);
    unsigned dst_off = (unsigned)(((int)rank * 256 + rb * 64 + jl) * 4);
    unsigned d0 = mapa_u32(hs_u + dst_off, 0);
    unsigned stride = mapa_u32(hs_u + dst_off, 1) - d0;
    // remote barrier base for this thread's target CTA (threads 0..7 only use it)
    unsigned rbar = (tid < 8) ? mapa_u32(barb, (unsigned)tid) : 0u;

    int ridx = ((jl >> 5) * 4 + rb) * 32 + (jl & 31);
    unsigned ib = 0, ib1 = 1;     // t%3, (t+1)%3
    unsigned parmask = 0;

    for (int t = 0; t < TT; ++t) {
        const float* cur = hs + ib * 2048;
        float xp = __ldg(&g_xproj[((size_t)(cbase + rb) * TT + t) * HH + jbase + jl]);

        // ---- recurrent GEMV slice: W in regs, h broadcast from SMEM ----
        const float* hb = cur + warp * 256;   // [4][64] for this warp's k range
        unsigned long long a00 = 0, a01 = 0, a02 = 0, a03 = 0;
        unsigned long long a10 = 0, a11 = 0, a12 = 0, a13 = 0;
#pragma unroll
        for (int m = 0; m < 16; ++m) {
            ulonglong2 h0 = *(const ulonglong2*)&hb[0 * 64 + m * 4];
            ulonglong2 h1 = *(const ulonglong2*)&hb[1 * 64 + m * 4];
            ulonglong2 h2 = *(const ulonglong2*)&hb[2 * 64 + m * 4];
            ulonglong2 h3 = *(const ulonglong2*)&hb[3 * 64 + m * 4];
            fma2(a00, w0r[2 * m], h0.x); fma2(a00, w0r[2 * m + 1], h0.y);
            fma2(a01, w0r[2 * m], h1.x); fma2(a01, w0r[2 * m + 1], h1.y);
            fma2(a02, w0r[2 * m], h2.x); fma2(a02, w0r[2 * m + 1], h2.y);
            fma2(a03, w0r[2 * m], h3.x); fma2(a03, w0r[2 * m + 1], h3.y);
            fma2(a10, w1r[2 * m], h0.x); fma2(a10, w1r[2 * m + 1], h0.y);
            fma2(a11, w1r[2 * m], h1.x); fma2(a11, w1r[2 * m + 1], h1.y);
            fma2(a12, w1r[2 * m], h2.x); fma2(a12, w1r[2 * m + 1], h2.y);
            fma2(a13, w1r[2 * m], h3.x); fma2(a13, w1r[2 * m + 1], h3.y);
        }
        red[warp * 256 + 0 * 32 + lane] = hadd2(a00);
        red[warp * 256 + 1 * 32 + lane] = hadd2(a01);
        red[warp * 256 + 2 * 32 + lane] = hadd2(a02);
        red[warp * 256 + 3 * 32 + lane] = hadd2(a03);
        red[warp * 256 + 4 * 32 + lane] = hadd2(a10);
        red[warp * 256 + 5 * 32 + lane] = hadd2(a11);
        red[warp * 256 + 6 * 32 + lane] = hadd2(a12);
        red[warp * 256 + 7 * 32 + lane] = hadd2(a13);
        __syncthreads();

        // ---- reduce, activate ----
        float s = 0.f;
#pragma unroll
        for (int w = 0; w < 8; ++w) s += red[w * 256 + ridx];
        float pre = s + bsl[jl] + xp;
        float hp = cur[(int)rank * 256 + rb * 64 + jl];
        float hn = (1.0f - ALPHA) * hp + ALPHA * fast_tanh(pre);

        if (t == TT - 1) hfinal[(size_t)(cbase + rb) * HH + jbase + jl] = hn;

        // ---- scatter h_{t+1} to all 8 CTAs' buffer ib1 (plain remote stores) ----
        float hpart = __shfl_xor_sync(0xffffffffu, hn, 1);
        unsigned dbase = d0 + ib1 * (2048u * 4u);
        if (!(jl & 1)) {
            unsigned long long val = pack2(hn, hpart);
#pragma unroll
            for (int r = 0; r < CL; ++r)
                st_cluster64(dbase + (unsigned)r * stride, val);
        }

        // all scatters issued -> one representative arrive per target CTA
        __syncthreads();
        if (tid < 8) {
            fence_cluster();                       // cumulative: releases ALL threads' stores
            mbar_arrive_remote(rbar + ib1 * 8u);   // arrive on CTA 'tid's barrier[ib1]
        }

        // ---- deferred output out_{t-1} = W_out . h_t (hides exchange latency) ----
        if (t > 0)
            do_out(cur, WoS, out, bo4, wb, og, rank, cbase, lane, t - 1);

        // ---- wait for all 8 CTAs' slices of h_{t+1} ----
        mbar_wait(barb + ib1 * 8u, (parmask >> ib1) & 1u);
        parmask ^= (1u << ib1);

        ib = ib1;
        ib1 = (ib1 == 2) ? 0u : ib1 + 1u;
    }

    // epilogue: out_{TT-1} from h_TT (buffer TT%3 == ib after loop)
    do_out(hs + ib * 2048, WoS, out, bo4, wb, og, rank, cbase, lane, TT - 1);
}

// ---------------------------------------------------------------------------
extern "C" void kernel_launch(void* const* d_in, const int* in_sizes, int n_in,
                              void* d_out, int out_size) {
    const float* inputs = (const float*)d_in[0];   // [B,T,I]
    const float* hidden = (const float*)d_in[1];   // [B,H]
    const float* W_in   = (const float*)d_in[2];   // [H,I]
    const float* W_rec  = (const float*)d_in[3];   // [H,H]
    const float* b      = (const float*)d_in[4];   // [H]
    const float* W_out  = (const float*)d_in[5];   // [O,H]
    const float* b_out  = (const float*)d_in[6];   // [O]

    float* out    = (float*)d_out;                 // [B,T,O]
    float* hfinal = out + (size_t)BB * TT * OO;    // [B,H]

    xproj_kernel<<<dim3(512, 8), 256>>>(inputs, W_in);

    const size_t smem_bytes = (size_t)SM_TOT * sizeof(float);
    cudaFuncSetAttribute(rnn_scan_kernel, cudaFuncAttributeMaxDynamicSharedMemorySize,
                         (int)smem_bytes);

    cudaLaunchConfig_t cfg = {};
    cfg.gridDim = dim3((BB / NB) * CL);   // 16 clusters * 8 CTAs = 128 blocks
    cfg.blockDim = dim3(256);
    cfg.dynamicSmemBytes = smem_bytes;
    cudaLaunchAttribute attrs[1];
    attrs[0].id = cudaLaunchAttributeClusterDimension;
    attrs[0].val.clusterDim.x = CL;
    attrs[0].val.clusterDim.y = 1;
    attrs[0].val.clusterDim.z = 1;
    cfg.attrs = attrs;
    cfg.numAttrs = 1;

    cudaLaunchKernelEx(&cfg, rnn_scan_kernel, hidden, W_rec, b, W_out, b_out, out, hfinal);
}